// round 5
// baseline (speedup 1.0000x reference)
#include <cuda_runtime.h>
#include <math.h>

#define CONF_TH 0.25f
#define NMS_TH  0.35f
#define FULL    0xffffffffu

static constexpr int N_IMG = 64;
static constexpr int HW    = 1024;   // 32*32
static constexpr int NCH   = 85;
static constexpr int NCLS  = 80;

// static scratch (allowed: __device__ globals, no allocation)
__device__ unsigned long long g_key[N_IMG * HW];
__device__ float4             g_box[N_IMG * HW];

// ============================================================
// Kernel A: decode. grid = 128 (2 slices/image), block = 128.
// Each thread decodes 4 consecutive pixels with float4 loads.
// ============================================================
__global__ __launch_bounds__(128, 8)
void decode_kernel(const float* __restrict__ in, float* __restrict__ out)
{
    const int n  = blockIdx.x >> 1;          // image
    const int s  = blockIdx.x & 1;           // slice
    const int p0 = s * 512 + threadIdx.x * 4; // first pixel (multiple of 4)

    const float4* base = (const float4*)(in + (size_t)n * NCH * HW) + (p0 >> 2);
    // channel c lives at base[c * 256]

    float4 pobj = base[0 * 256];
    float4 r0   = base[1 * 256];
    float4 r1   = base[2 * 256];
    float4 r2   = base[3 * 256];
    float4 r3   = base[4 * 256];

    // per-component argmax over 80 classes (first occurrence via strict >)
    float4 bv = make_float4(-INFINITY, -INFINITY, -INFINITY, -INFINITY);
    int4   bj = make_int4(0, 0, 0, 0);
    #pragma unroll 10
    for (int c = 0; c < NCLS; c++) {
        float4 v = base[(5 + c) * 256];
        if (v.x > bv.x) { bv.x = v.x; bj.x = c; }
        if (v.y > bv.y) { bv.y = v.y; bj.y = c; }
        if (v.z > bv.z) { bv.z = v.z; bj.z = c; }
        if (v.w > bv.w) { bv.w = v.w; bj.w = c; }
    }

    float sc[4]   = { pobj.x * bv.x, pobj.y * bv.y, pobj.z * bv.z, pobj.w * bv.w };
    float rr0[4]  = { r0.x, r0.y, r0.z, r0.w };
    float rr1[4]  = { r1.x, r1.y, r1.z, r1.w };
    float rr2[4]  = { r2.x, r2.y, r2.z, r2.w };
    float rr3[4]  = { r3.x, r3.y, r3.z, r3.w };
    int   cl[4]   = { bj.x, bj.y, bj.z, bj.w };

    float vals[24];
    unsigned long long keys[4];
    float4 boxes[4];

    #pragma unroll
    for (int l = 0; l < 4; l++) {
        int p = p0 + l;
        float gx = (float)(p & 31);
        float gy = (float)(p >> 5);
        float bcx = (tanhf(rr0[l]) + gx) * (1.0f / 32.0f);
        float bcy = (tanhf(rr1[l]) + gy) * (1.0f / 32.0f);
        float bw  = 1.0f / (1.0f + expf(-rr2[l]));
        float bh  = 1.0f / (1.0f + expf(-rr3[l]));
        float x1 = bcx - 0.5f * bw;
        float y1 = bcy - 0.5f * bh;
        float x2 = bcx + 0.5f * bw;
        float y2 = bcy + 0.5f * bh;

        vals[l * 6 + 0] = x1; vals[l * 6 + 1] = y1;
        vals[l * 6 + 2] = x2; vals[l * 6 + 3] = y2;
        vals[l * 6 + 4] = sc[l]; vals[l * 6 + 5] = (float)cl[l];

        boxes[l] = make_float4(x1, y1, x2, y2);

        bool cand = sc[l] > CONF_TH;
        unsigned u = __float_as_uint(sc[l]);
        u = (u & 0x80000000u) ? ~u : (u | 0x80000000u);   // ascending-sortable
        keys[l] = cand
            ? (((unsigned long long)(unsigned)cl[l] << 42)
               | ((unsigned long long)(~u) << 10)
               | (unsigned)p)
            : (0x8000000000000000ull | (unsigned)p);
    }

    // boxes+score+cls to out: 24 contiguous floats = 6 float4 stores
    float4* ob4 = (float4*)(out + ((size_t)n * HW + p0) * 6);
    #pragma unroll
    for (int q = 0; q < 6; q++)
        ob4[q] = make_float4(vals[q * 4 + 0], vals[q * 4 + 1], vals[q * 4 + 2], vals[q * 4 + 3]);

    // scratch writes (vectorized)
    ulonglong2* kp = (ulonglong2*)&g_key[(size_t)n * HW + p0];
    kp[0] = make_ulonglong2(keys[0], keys[1]);
    kp[1] = make_ulonglong2(keys[2], keys[3]);
    float4* bp = &g_box[(size_t)n * HW + p0];
    #pragma unroll
    for (int l = 0; l < 4; l++) bp[l] = boxes[l];
}

// ============================================================
// Kernel B: per-class NMS. grid = 64, block = 1024.
// ============================================================
__device__ __forceinline__ unsigned long long bitonic_shfl_step(
    unsigned long long key, int j, bool up, int t)
{
    unsigned long long p = __shfl_xor_sync(FULL, key, j);
    bool low     = ((t & j) == 0);
    bool takeMin = (low == up);
    bool swap    = takeMin ? (p < key) : (p > key);
    return swap ? p : key;
}

__global__ __launch_bounds__(1024, 1)
void nms_kernel(float* __restrict__ out)
{
    __shared__ float4             sbox[HW];
    __shared__ unsigned long long list[HW];
    __shared__ unsigned           keepS[HW];
    __shared__ unsigned           state[HW];
    __shared__ unsigned           cnt[NCLS];
    __shared__ unsigned           segb[NCLS];
    __shared__ unsigned           curs[NCLS];

    const int n    = blockIdx.x;
    const int t    = threadIdx.x;
    const int lane = t & 31;
    const int wid  = t >> 5;

    unsigned long long key = g_key[(size_t)n * HW + t];
    sbox[t]  = g_box[(size_t)n * HW + t];
    keepS[t] = 0u;
    state[t] = 0u;
    if (t < NCLS) cnt[t] = 0u;

    bool cand = (key >> 63) == 0ull;
    int  bi   = (int)((key >> 42) & 0x7Fu);
    __syncthreads();

    // pass 1: per-class counts
    if (cand) atomicAdd(&cnt[bi], 1u);
    __syncthreads();

    // exclusive prefix over 80 counts (warp 0)
    if (t < 32) {
        unsigned c0 = cnt[t];
        unsigned c1 = (t + 32 < NCLS) ? cnt[t + 32] : 0u;
        unsigned c2 = (t + 64 < NCLS) ? cnt[t + 64] : 0u;

        unsigned x = c0;
        #pragma unroll
        for (int d = 1; d < 32; d <<= 1) { unsigned y = __shfl_up_sync(FULL, x, d); if (lane >= d) x += y; }
        unsigned e0 = x - c0;
        unsigned tot0 = __shfl_sync(FULL, x, 31);

        x = c1;
        #pragma unroll
        for (int d = 1; d < 32; d <<= 1) { unsigned y = __shfl_up_sync(FULL, x, d); if (lane >= d) x += y; }
        unsigned e1 = tot0 + x - c1;
        unsigned tot1 = tot0 + __shfl_sync(FULL, x, 31);

        x = c2;
        #pragma unroll
        for (int d = 1; d < 32; d <<= 1) { unsigned y = __shfl_up_sync(FULL, x, d); if (lane >= d) x += y; }
        unsigned e2 = tot1 + x - c2;

        segb[t] = e0;  curs[t] = e0;
        if (t + 32 < NCLS) { segb[t + 32] = e1; curs[t + 32] = e1; }
        if (t + 64 < NCLS) { segb[t + 64] = e2; curs[t + 64] = e2; }
    }
    __syncthreads();

    // pass 2: scatter keys into class segments
    if (cand) {
        unsigned r = atomicAdd(&curs[bi], 1u);
        list[r] = key;
    }
    __syncthreads();

    // warp-per-class greedy NMS (no barriers)
    for (int c = wid; c < NCLS; c += 32) {
        int m  = (int)cnt[c];
        if (m == 0) continue;
        int bs = (int)segb[c];

        if (m <= 32) {
            unsigned long long kk = (lane < m) ? list[bs + lane] : ~0ull;
            #pragma unroll
            for (int k = 2; k <= 32; k <<= 1) {
                #pragma unroll
                for (int j = k >> 1; j >= 1; j >>= 1)
                    kk = bitonic_shfl_step(kk, j, (lane & k) == 0, lane);
            }
            int pos = (int)(kk & 0x3FFu);
            float4 b4 = sbox[pos];
            float  ar = (b4.z - b4.x) * (b4.w - b4.y);

            unsigned removed = 0u, keepB = 0u;
            for (int i = 0; i < m; i++) {
                if ((removed >> i) & 1u) continue;     // uniform across warp
                keepB |= 1u << i;
                float wx1 = __shfl_sync(FULL, b4.x, i);
                float wy1 = __shfl_sync(FULL, b4.y, i);
                float wx2 = __shfl_sync(FULL, b4.z, i);
                float wy2 = __shfl_sync(FULL, b4.w, i);
                float wa  = __shfl_sync(FULL, ar,   i);
                float iw = fminf(b4.z, wx2) - fmaxf(b4.x, wx1);
                float ih = fminf(b4.w, wy2) - fmaxf(b4.y, wy1);
                iw = fmaxf(iw, 0.0f);
                ih = fmaxf(ih, 0.0f);
                float inter = iw * ih;
                bool s = (lane > i) && (lane < m) &&
                         (inter > NMS_TH * (ar + wa - inter + 1e-9f));
                removed |= __ballot_sync(FULL, s);
            }
            if (lane < m && ((keepB >> lane) & 1u)) keepS[pos] = 1u;
        } else {
            // generic fallback (rare): iterative select-min + suppress
            while (true) {
                unsigned long long bestk = ~0ull;
                for (int idx = lane; idx < m; idx += 32)
                    if (state[bs + idx] == 0u) {
                        unsigned long long k2 = list[bs + idx];
                        if (k2 < bestk) bestk = k2;
                    }
                #pragma unroll
                for (int d = 16; d >= 1; d >>= 1) {
                    unsigned long long o = __shfl_xor_sync(FULL, bestk, d);
                    if (o < bestk) bestk = o;
                }
                if (bestk == ~0ull) break;
                int wpos = (int)(bestk & 0x3FFu);
                float4 wb = sbox[wpos];
                float  wa = (wb.z - wb.x) * (wb.w - wb.y);
                for (int idx = lane; idx < m; idx += 32) {
                    if (state[bs + idx] != 0u) continue;
                    unsigned long long k2 = list[bs + idx];
                    if (k2 == bestk) { state[bs + idx] = 1u; keepS[wpos] = 1u; continue; }
                    int p2 = (int)(k2 & 0x3FFu);
                    float4 b2 = sbox[p2];
                    float a2 = (b2.z - b2.x) * (b2.w - b2.y);
                    float iw = fminf(b2.z, wb.z) - fmaxf(b2.x, wb.x);
                    float ih = fminf(b2.w, wb.w) - fmaxf(b2.y, wb.y);
                    iw = fmaxf(iw, 0.0f);
                    ih = fmaxf(ih, 0.0f);
                    float inter = iw * ih;
                    if (inter > NMS_TH * (a2 + wa - inter + 1e-9f)) state[bs + idx] = 2u;
                }
                __syncwarp(FULL);
            }
        }
    }
    __syncthreads();

    out[(size_t)N_IMG * HW * 6 + (size_t)n * HW + t] = (float)keepS[t];
}

extern "C" void kernel_launch(void* const* d_in, const int* in_sizes, int n_in,
                              void* d_out, int out_size)
{
    const float* in = (const float*)d_in[0];
    float* out = (float*)d_out;
    decode_kernel<<<N_IMG * 2, 128>>>(in, out);
    nms_kernel<<<N_IMG, 1024>>>(out);
}